// round 2
// baseline (speedup 1.0000x reference)
#include <cuda_runtime.h>
#include <cuda_bf16.h>
#include <cstdint>

// Problem constants
#define EMBED   1024
#define NHEADS  16
#define HDIM    64
#define BATCH   4
#define SEQ     2048
#define QKSCALE 0.125f   // 1/sqrt(64)

// Scratch (device globals: allocation-free per harness rules)
__device__ float g_qkv[(size_t)BATCH * SEQ * 3 * EMBED];  // [B*N, 3C] ~100.7 MB
__device__ float g_att[(size_t)BATCH * SEQ * EMBED];      // [B*N, C]  ~33.5 MB

// ---------------------------------------------------------------------------
// GEMM: C[M,N] = A[M,K] @ B[K,N] + bias[N]
// 128x128 block tile, BK=16, 8x8 microtile, 256 threads.
// ---------------------------------------------------------------------------
__global__ __launch_bounds__(256, 2)
void gemm_bias_kernel(const float* __restrict__ A, const float* __restrict__ B,
                      const float* __restrict__ bias, float* __restrict__ C,
                      int M, int N, int K)
{
    __shared__ float As[16][132];   // transposed: As[k][m], pad 4 to reduce conflicts
    __shared__ float Bs[16][128];   // natural:    Bs[k][n]

    const int t  = threadIdx.x;
    const int m0 = blockIdx.y * 128;
    const int n0 = blockIdx.x * 128;
    const int ty = t >> 4;          // 0..15
    const int tx = t & 15;          // 0..15

    // A load mapping: each thread loads 8 consecutive floats of one row
    const int arow = t >> 1;            // 0..127
    const int acol = (t & 1) * 8;       // 0 or 8
    // B load mapping: each thread loads 8 consecutive floats of one k-row
    const int brow = t >> 4;            // 0..15
    const int bcol = (t & 15) * 8;      // 0..120

    const float* Aptr = A + (size_t)(m0 + arow) * K + acol;
    const float* Bptr = B + (size_t)brow * N + n0 + bcol;

    float acc[8][8];
#pragma unroll
    for (int i = 0; i < 8; i++)
#pragma unroll
        for (int j = 0; j < 8; j++) acc[i][j] = 0.0f;

    for (int k0 = 0; k0 < K; k0 += 16) {
        // Global loads into registers (latency overlaps with prior compute/barrier)
        float4 a0 = *(const float4*)(Aptr + k0);
        float4 a1 = *(const float4*)(Aptr + k0 + 4);
        float4 b0 = *(const float4*)(Bptr + (size_t)k0 * N);
        float4 b1 = *(const float4*)(Bptr + (size_t)k0 * N + 4);

        __syncthreads();   // previous tile's compute done

        // Store A transposed
        As[acol + 0][arow] = a0.x;
        As[acol + 1][arow] = a0.y;
        As[acol + 2][arow] = a0.z;
        As[acol + 3][arow] = a0.w;
        As[acol + 4][arow] = a1.x;
        As[acol + 5][arow] = a1.y;
        As[acol + 6][arow] = a1.z;
        As[acol + 7][arow] = a1.w;
        // Store B natural (vectorized)
        *(float4*)&Bs[brow][bcol]     = b0;
        *(float4*)&Bs[brow][bcol + 4] = b1;

        __syncthreads();

#pragma unroll
        for (int kk = 0; kk < 16; kk++) {
            float4 ar0 = *(const float4*)&As[kk][ty * 8];
            float4 ar1 = *(const float4*)&As[kk][ty * 8 + 4];
            float4 br0 = *(const float4*)&Bs[kk][tx * 8];
            float4 br1 = *(const float4*)&Bs[kk][tx * 8 + 4];
            float a[8] = {ar0.x, ar0.y, ar0.z, ar0.w, ar1.x, ar1.y, ar1.z, ar1.w};
            float b[8] = {br0.x, br0.y, br0.z, br0.w, br1.x, br1.y, br1.z, br1.w};
#pragma unroll
            for (int i = 0; i < 8; i++)
#pragma unroll
                for (int j = 0; j < 8; j++)
                    acc[i][j] = fmaf(a[i], b[j], acc[i][j]);
        }
    }

    // Epilogue: + bias, vectorized stores
    float bi[8];
#pragma unroll
    for (int j = 0; j < 8; j++) bi[j] = bias[n0 + tx * 8 + j];

#pragma unroll
    for (int i = 0; i < 8; i++) {
        const int row = m0 + ty * 8 + i;
        float* Crow = C + (size_t)row * N + n0 + tx * 8;
        float4 o0, o1;
        o0.x = acc[i][0] + bi[0]; o0.y = acc[i][1] + bi[1];
        o0.z = acc[i][2] + bi[2]; o0.w = acc[i][3] + bi[3];
        o1.x = acc[i][4] + bi[4]; o1.y = acc[i][5] + bi[5];
        o1.z = acc[i][6] + bi[6]; o1.w = acc[i][7] + bi[7];
        *(float4*)(Crow)     = o0;
        *(float4*)(Crow + 4) = o1;
    }
}

// ---------------------------------------------------------------------------
// Flash attention (fp32): one block per (64-query tile, head, batch).
// Streams 64-key tiles with online softmax computed IN REGISTERS via
// half-warp shuffles (threads with the same ty are 16 consecutive lanes).
// qkv layout: [B, N, 3, H, D] flattened -> row stride 3072; q:+0, k:+1024, v:+2048
// out layout: [B, N, H*D] = [B*N, 1024]
// ---------------------------------------------------------------------------
__global__ __launch_bounds__(256)
void attn_kernel(const float* __restrict__ qkv, float* __restrict__ out)
{
    extern __shared__ float sm[];
    float* Qs = sm;                 // [64][68]  Qs[d*68 + i]  (transposed, scaled)
    float* Ks = Qs + 64 * 68;       // [64][68]  Ks[d*68 + j]  (transposed)
    float* Ps = Ks + 64 * 68;       // [64][65]  Ps[i*65 + j]  (probabilities)
    float* Vs = Ps + 64 * 65;       // [64][64]  Vs[j*64 + d]  (natural)

    const int t  = threadIdx.x;
    const int q0 = blockIdx.x * 64;
    const int h  = blockIdx.y;
    const int b  = blockIdx.z;
    const int ty = t >> 4;            // 0..15 -> S/O rows ty*4..ty*4+3
    const int tx = t & 15;            // 0..15 -> S/O cols tx*4..tx*4+3

    const size_t rstride = 3 * EMBED;  // 3072
    const float* base = qkv + (size_t)b * SEQ * rstride + h * HDIM;

    // Load Q tile (scaled), transposed into Qs[d][i]
    {
        const int i  = t >> 2;            // query row 0..63
        const int cg = (t & 3) * 16;      // dim group start
        const float* qp = base + (size_t)(q0 + i) * rstride + cg;
#pragma unroll
        for (int x = 0; x < 16; x += 4) {
            float4 v = *(const float4*)(qp + x);
            Qs[(cg + x + 0) * 68 + i] = v.x * QKSCALE;
            Qs[(cg + x + 1) * 68 + i] = v.y * QKSCALE;
            Qs[(cg + x + 2) * 68 + i] = v.z * QKSCALE;
            Qs[(cg + x + 3) * 68 + i] = v.w * QKSCALE;
        }
    }

    // Running softmax stats (replicated across the 16 threads of a row group)
    float rm[4], rl[4];
#pragma unroll
    for (int i = 0; i < 4; i++) { rm[i] = -1e30f; rl[i] = 0.0f; }

    float oacc[4][4];
#pragma unroll
    for (int i = 0; i < 4; i++)
#pragma unroll
        for (int j = 0; j < 4; j++) oacc[i][j] = 0.0f;

    for (int kt = 0; kt < SEQ / 64; kt++) {
        __syncthreads();   // previous PV reads of Ks/Vs/Ps done; Qs visible (kt=0)

        // Load K (transposed) and V (natural) tiles
        {
            const int j  = t >> 2;
            const int cg = (t & 3) * 16;
            const float* kp = base + (size_t)(kt * 64 + j) * rstride + EMBED + cg;
            const float* vp = kp + EMBED;
#pragma unroll
            for (int x = 0; x < 16; x += 4) {
                float4 kv = *(const float4*)(kp + x);
                Ks[(cg + x + 0) * 68 + j] = kv.x;
                Ks[(cg + x + 1) * 68 + j] = kv.y;
                Ks[(cg + x + 2) * 68 + j] = kv.z;
                Ks[(cg + x + 3) * 68 + j] = kv.w;
                float4 vv = *(const float4*)(vp + x);
                *(float4*)&Vs[j * 64 + cg + x] = vv;
            }
        }
        __syncthreads();

        // S = (Q*scale) @ K^T  -> 4x4 fragment in registers
        float sacc[4][4];
#pragma unroll
        for (int i = 0; i < 4; i++)
#pragma unroll
            for (int j = 0; j < 4; j++) sacc[i][j] = 0.0f;

#pragma unroll 8
        for (int d = 0; d < 64; d++) {
            float4 a  = *(const float4*)&Qs[d * 68 + ty * 4];
            float4 bq = *(const float4*)&Ks[d * 68 + tx * 4];
            float av[4] = {a.x, a.y, a.z, a.w};
            float bv[4] = {bq.x, bq.y, bq.z, bq.w};
#pragma unroll
            for (int i = 0; i < 4; i++)
#pragma unroll
                for (int j = 0; j < 4; j++)
                    sacc[i][j] = fmaf(av[i], bv[j], sacc[i][j]);
        }

        // --- In-register online softmax ---
        // Row group = 16 threads with the same ty = 16 consecutive lanes of a
        // half-warp. shfl_xor over strides 1,2,4,8 stays inside the group.
        float fac[4];
#pragma unroll
        for (int i = 0; i < 4; i++) {
            float mx = fmaxf(fmaxf(sacc[i][0], sacc[i][1]),
                             fmaxf(sacc[i][2], sacc[i][3]));
#pragma unroll
            for (int s = 1; s < 16; s <<= 1)
                mx = fmaxf(mx, __shfl_xor_sync(0xFFFFFFFFu, mx, s));
            mx = fmaxf(mx, rm[i]);                 // new running max
            fac[i] = __expf(rm[i] - mx);
            rm[i] = mx;

            float ls = 0.0f;
#pragma unroll
            for (int j = 0; j < 4; j++) {
                float p = __expf(sacc[i][j] - mx);
                sacc[i][j] = p;
                ls += p;
            }
#pragma unroll
            for (int s = 1; s < 16; s <<= 1)
                ls += __shfl_xor_sync(0xFFFFFFFFu, ls, s);
            rl[i] = rl[i] * fac[i] + ls;
        }

        // Write probabilities to smem for the PV broadcast-read pattern
#pragma unroll
        for (int i = 0; i < 4; i++)
#pragma unroll
            for (int j = 0; j < 4; j++)
                Ps[(ty * 4 + i) * 65 + tx * 4 + j] = sacc[i][j];

        // Rescale existing O while P lands in smem
#pragma unroll
        for (int i = 0; i < 4; i++)
#pragma unroll
            for (int j = 0; j < 4; j++) oacc[i][j] *= fac[i];

        __syncthreads();

        // O += P @ V
#pragma unroll 8
        for (int j = 0; j < 64; j++) {
            float p[4];
#pragma unroll
            for (int i = 0; i < 4; i++) p[i] = Ps[(ty * 4 + i) * 65 + j];  // broadcast
            float4 v = *(const float4*)&Vs[j * 64 + tx * 4];
            float vv[4] = {v.x, v.y, v.z, v.w};
#pragma unroll
            for (int i = 0; i < 4; i++)
#pragma unroll
                for (int jj = 0; jj < 4; jj++)
                    oacc[i][jj] = fmaf(p[i], vv[jj], oacc[i][jj]);
        }
    }

    // Normalize and write out[(b*SEQ + q)*EMBED + h*HDIM + d]
#pragma unroll
    for (int i = 0; i < 4; i++) {
        const float linv = 1.0f / rl[i];
        const size_t row = (size_t)b * SEQ + q0 + ty * 4 + i;
        float4 o;
        o.x = oacc[i][0] * linv;
        o.y = oacc[i][1] * linv;
        o.z = oacc[i][2] * linv;
        o.w = oacc[i][3] * linv;
        *(float4*)(out + row * EMBED + h * HDIM + tx * 4) = o;
    }
}

// ---------------------------------------------------------------------------
// Launch
// ---------------------------------------------------------------------------
extern "C" void kernel_launch(void* const* d_in, const int* in_sizes, int n_in,
                              void* d_out, int out_size)
{
    const float* x      = (const float*)d_in[0];  // [4,2048,1024]
    const float* w_qkv  = (const float*)d_in[1];  // [1024,3072]
    const float* b_qkv  = (const float*)d_in[2];  // [3072]
    const float* w_proj = (const float*)d_in[3];  // [1024,1024]
    const float* b_proj = (const float*)d_in[4];  // [1024]
    float* out = (float*)d_out;                   // [8192,1024]

    float *g1 = nullptr, *g2 = nullptr;
    cudaGetSymbolAddress((void**)&g1, g_qkv);
    cudaGetSymbolAddress((void**)&g2, g_att);

    const int M = BATCH * SEQ;   // 8192

    // 1) QKV projection: [8192,1024] @ [1024,3072] + b
    gemm_bias_kernel<<<dim3(3 * EMBED / 128, M / 128), 256>>>(
        x, w_qkv, b_qkv, g1, M, 3 * EMBED, EMBED);

    // 2) Flash attention
    size_t smem = (size_t)(64 * 68 * 2 + 64 * 65 + 64 * 64) * sizeof(float);
    cudaFuncSetAttribute(attn_kernel, cudaFuncAttributeMaxDynamicSharedMemorySize, (int)smem);
    attn_kernel<<<dim3(SEQ / 64, NHEADS, BATCH), 256, smem>>>(g1, g2);

    // 3) Output projection: [8192,1024] @ [1024,1024] + b
    gemm_bias_kernel<<<dim3(EMBED / 128, M / 128), 256>>>(
        g2, w_proj, b_proj, out, M, EMBED, EMBED);
}

// round 7
// speedup vs baseline: 1.2345x; 1.2345x over previous
#include <cuda_runtime.h>
#include <cuda_bf16.h>
#include <cstdint>

// Problem constants
#define EMBED   1024
#define NHEADS  16
#define HDIM    64
#define BATCH   4
#define SEQ     2048
#define QKSCALE 0.125f   // 1/sqrt(64)

// Scratch (device globals: allocation-free per harness rules)
__device__ float g_qkv[(size_t)BATCH * SEQ * 3 * EMBED];  // [B*N, 3C]
__device__ float g_att[(size_t)BATCH * SEQ * EMBED];      // [B*N, C]

// round fp32 -> tf32 (RNA) — plain sm_80+ instruction, no 'a' gating
__device__ __forceinline__ float f2tf32f(float x) {
    uint32_t r;
    asm("cvt.rna.tf32.f32 %0, %1;" : "=r"(r) : "f"(x));
    return __uint_as_float(r);
}

// m16n8k8 tf32 MMA (sm_80+ baseline PTX; HMMA on sm_103)
__device__ __forceinline__ void mma_tf32(float* d, const uint32_t* a, const uint32_t* b) {
    asm volatile(
        "mma.sync.aligned.m16n8k8.row.col.f32.tf32.tf32.f32 "
        "{%0,%1,%2,%3}, {%4,%5,%6,%7}, {%8,%9}, {%0,%1,%2,%3};"
        : "+f"(d[0]), "+f"(d[1]), "+f"(d[2]), "+f"(d[3])
        : "r"(a[0]), "r"(a[1]), "r"(a[2]), "r"(a[3]), "r"(b[0]), "r"(b[1]));
}

// ===========================================================================
// tf32 mma.sync GEMM: C[M,N] = A[M,K] @ W[K,N] + bias[N]
// 128x128 block, BK=32, 8 warps in 2x4 grid (64x32 warp tiles),
// double-buffered SMEM with register staging.
// SMEM pitches chosen for conflict-free fragment loads:
//   As[m][k]: pitch 36  -> A-frag bank = (4g + t) % 32, bijective
//   Bs[k][n]: pitch 136 -> B-frag bank = (8t + g) % 32, bijective
// ===========================================================================
#define AS_PITCH 36
#define BS_PITCH 136
#define AS_STRIDE (128 * AS_PITCH)   // 4608 floats per stage
#define BS_STRIDE (32 * BS_PITCH)    // 4352 floats per stage
#define GM_SMEM ((2 * AS_STRIDE + 2 * BS_STRIDE) * 4)  // 71680 bytes

__global__ __launch_bounds__(256)
void gemm_mma_kernel(const float* __restrict__ A, const float* __restrict__ W,
                     const float* __restrict__ bias, float* __restrict__ C,
                     int M, int N, int K)
{
    extern __shared__ float sh[];
    float* As = sh;                    // [2][128][36]
    float* Bs = sh + 2 * AS_STRIDE;    // [2][32][136]

    const int t    = threadIdx.x;
    const int wid  = t >> 5;
    const int lane = t & 31;
    const int wm   = (wid >> 2) * 64;  // warp m offset: 0 or 64
    const int wn   = (wid & 3) * 32;   // warp n offset: 0,32,64,96
    const int m0   = blockIdx.y * 128;
    const int n0   = blockIdx.x * 128;
    const int g    = lane >> 2;        // group id 0..7
    const int tq   = lane & 3;         // thread-in-group 0..3

    // Global load mapping (per 128x32 A / 32x128 B chunk, 16 floats/thread)
    const int arow = t >> 1;            // 0..127
    const int acol = (t & 1) * 16;      // 0 or 16 (k within chunk)
    const int brow = t >> 3;            // 0..31   (k within chunk)
    const int bcol = (t & 7) * 16;      // 0..112  (n within tile)

    const float* Ap = A + (size_t)(m0 + arow) * K + acol;
    const float* Wp = W + (size_t)brow * N + n0 + bcol;

    float acc[16][4];
#pragma unroll
    for (int i = 0; i < 16; i++)
#pragma unroll
        for (int j = 0; j < 4; j++) acc[i][j] = 0.0f;

    float4 ra[4], rb[4];

    // ---- prologue: chunk 0 -> regs -> smem stage 0 ----
#pragma unroll
    for (int i = 0; i < 4; i++) {
        ra[i] = *(const float4*)(Ap + i * 4);
        rb[i] = *(const float4*)(Wp + i * 4);
    }
    {
        float* ad = As + arow * AS_PITCH + acol;
        float* bd = Bs + brow * BS_PITCH + bcol;
#pragma unroll
        for (int i = 0; i < 4; i++) {
            float4 va, vb;
            va.x = f2tf32f(ra[i].x); va.y = f2tf32f(ra[i].y);
            va.z = f2tf32f(ra[i].z); va.w = f2tf32f(ra[i].w);
            vb.x = f2tf32f(rb[i].x); vb.y = f2tf32f(rb[i].y);
            vb.z = f2tf32f(rb[i].z); vb.w = f2tf32f(rb[i].w);
            *(float4*)(ad + i * 4) = va;
            *(float4*)(bd + i * 4) = vb;
        }
    }
    __syncthreads();

    const int nch = K >> 5;   // 32-float chunks
    for (int ci = 0; ci < nch; ci++) {
        const int s = ci & 1;

        // Prefetch next chunk into registers (latency hidden by compute)
        if (ci + 1 < nch) {
            const int k0 = (ci + 1) << 5;
#pragma unroll
            for (int i = 0; i < 4; i++) {
                ra[i] = *(const float4*)(Ap + k0 + i * 4);
                rb[i] = *(const float4*)(Wp + (size_t)k0 * N + i * 4);
            }
        }

        // ---- compute on stage s ----
        const float* as = As + s * AS_STRIDE;
        const float* bs = Bs + s * BS_STRIDE;
#pragma unroll
        for (int k8 = 0; k8 < 4; k8++) {
            uint32_t af[4][4], bf[4][2];
#pragma unroll
            for (int mi = 0; mi < 4; mi++) {
                const float* ap = as + (wm + mi * 16 + g) * AS_PITCH + k8 * 8 + tq;
                af[mi][0] = __float_as_uint(ap[0]);
                af[mi][1] = __float_as_uint(ap[8 * AS_PITCH]);
                af[mi][2] = __float_as_uint(ap[4]);
                af[mi][3] = __float_as_uint(ap[8 * AS_PITCH + 4]);
            }
#pragma unroll
            for (int ni = 0; ni < 4; ni++) {
                const float* bp = bs + (k8 * 8 + tq) * BS_PITCH + wn + ni * 8 + g;
                bf[ni][0] = __float_as_uint(bp[0]);
                bf[ni][1] = __float_as_uint(bp[4 * BS_PITCH]);
            }
#pragma unroll
            for (int mi = 0; mi < 4; mi++)
#pragma unroll
                for (int ni = 0; ni < 4; ni++)
                    mma_tf32(acc[mi * 4 + ni], af[mi], bf[ni]);
        }

        // ---- store next chunk into the other stage ----
        if (ci + 1 < nch) {
            float* ad = As + (s ^ 1) * AS_STRIDE + arow * AS_PITCH + acol;
            float* bd = Bs + (s ^ 1) * BS_STRIDE + brow * BS_PITCH + bcol;
#pragma unroll
            for (int i = 0; i < 4; i++) {
                float4 va, vb;
                va.x = f2tf32f(ra[i].x); va.y = f2tf32f(ra[i].y);
                va.z = f2tf32f(ra[i].z); va.w = f2tf32f(ra[i].w);
                vb.x = f2tf32f(rb[i].x); vb.y = f2tf32f(rb[i].y);
                vb.z = f2tf32f(rb[i].z); vb.w = f2tf32f(rb[i].w);
                *(float4*)(ad + i * 4) = va;
                *(float4*)(bd + i * 4) = vb;
            }
        }
        __syncthreads();
    }

    // ---- epilogue: bias + store ----
    // D frag: c0:(g,2t) c1:(g,2t+1) c2:(g+8,2t) c3:(g+8,2t+1)
#pragma unroll
    for (int mi = 0; mi < 4; mi++) {
#pragma unroll
        for (int ni = 0; ni < 4; ni++) {
            const int col  = n0 + wn + ni * 8 + tq * 2;
            const float2 bv = *(const float2*)(bias + col);
            const int row1 = m0 + wm + mi * 16 + g;
            const float* a4 = acc[mi * 4 + ni];
            float2 o1, o2;
            o1.x = a4[0] + bv.x; o1.y = a4[1] + bv.y;
            o2.x = a4[2] + bv.x; o2.y = a4[3] + bv.y;
            *(float2*)(C + (size_t)row1 * N + col)       = o1;
            *(float2*)(C + (size_t)(row1 + 8) * N + col) = o2;
        }
    }
}

// ---------------------------------------------------------------------------
// Flash attention (fp32 SIMT): one block per (64-query tile, head, batch).
// In-register online softmax via half-warp shuffles. (Verified: R2 pass,
// rel_err 1.2e-6.)
// ---------------------------------------------------------------------------
__global__ __launch_bounds__(256)
void attn_kernel(const float* __restrict__ qkv, float* __restrict__ out)
{
    extern __shared__ float sm[];
    float* Qs = sm;                 // [64][68]  Qs[d*68 + i]
    float* Ks = Qs + 64 * 68;       // [64][68]  Ks[d*68 + j]
    float* Ps = Ks + 64 * 68;       // [64][65]  Ps[i*65 + j]
    float* Vs = Ps + 64 * 65;       // [64][64]  Vs[j*64 + d]

    const int t  = threadIdx.x;
    const int q0 = blockIdx.x * 64;
    const int h  = blockIdx.y;
    const int b  = blockIdx.z;
    const int ty = t >> 4;
    const int tx = t & 15;

    const size_t rstride = 3 * EMBED;
    const float* base = qkv + (size_t)b * SEQ * rstride + h * HDIM;

    {
        const int i  = t >> 2;
        const int cg = (t & 3) * 16;
        const float* qp = base + (size_t)(q0 + i) * rstride + cg;
#pragma unroll
        for (int x = 0; x < 16; x += 4) {
            float4 v = *(const float4*)(qp + x);
            Qs[(cg + x + 0) * 68 + i] = v.x * QKSCALE;
            Qs[(cg + x + 1) * 68 + i] = v.y * QKSCALE;
            Qs[(cg + x + 2) * 68 + i] = v.z * QKSCALE;
            Qs[(cg + x + 3) * 68 + i] = v.w * QKSCALE;
        }
    }

    float rm[4], rl[4];
#pragma unroll
    for (int i = 0; i < 4; i++) { rm[i] = -1e30f; rl[i] = 0.0f; }

    float oacc[4][4];
#pragma unroll
    for (int i = 0; i < 4; i++)
#pragma unroll
        for (int j = 0; j < 4; j++) oacc[i][j] = 0.0f;

    for (int kt = 0; kt < SEQ / 64; kt++) {
        __syncthreads();

        {
            const int j  = t >> 2;
            const int cg = (t & 3) * 16;
            const float* kp = base + (size_t)(kt * 64 + j) * rstride + EMBED + cg;
            const float* vp = kp + EMBED;
#pragma unroll
            for (int x = 0; x < 16; x += 4) {
                float4 kv = *(const float4*)(kp + x);
                Ks[(cg + x + 0) * 68 + j] = kv.x;
                Ks[(cg + x + 1) * 68 + j] = kv.y;
                Ks[(cg + x + 2) * 68 + j] = kv.z;
                Ks[(cg + x + 3) * 68 + j] = kv.w;
                float4 vv = *(const float4*)(vp + x);
                *(float4*)&Vs[j * 64 + cg + x] = vv;
            }
        }
        __syncthreads();

        float sacc[4][4];
#pragma unroll
        for (int i = 0; i < 4; i++)
#pragma unroll
            for (int j = 0; j < 4; j++) sacc[i][j] = 0.0f;

#pragma unroll 8
        for (int d = 0; d < 64; d++) {
            float4 a  = *(const float4*)&Qs[d * 68 + ty * 4];
            float4 bq = *(const float4*)&Ks[d * 68 + tx * 4];
            float av[4] = {a.x, a.y, a.z, a.w};
            float bv[4] = {bq.x, bq.y, bq.z, bq.w};
#pragma unroll
            for (int i = 0; i < 4; i++)
#pragma unroll
                for (int j = 0; j < 4; j++)
                    sacc[i][j] = fmaf(av[i], bv[j], sacc[i][j]);
        }

        float fac[4];
#pragma unroll
        for (int i = 0; i < 4; i++) {
            float mx = fmaxf(fmaxf(sacc[i][0], sacc[i][1]),
                             fmaxf(sacc[i][2], sacc[i][3]));
#pragma unroll
            for (int s = 1; s < 16; s <<= 1)
                mx = fmaxf(mx, __shfl_xor_sync(0xFFFFFFFFu, mx, s));
            mx = fmaxf(mx, rm[i]);
            fac[i] = __expf(rm[i] - mx);
            rm[i] = mx;

            float ls = 0.0f;
#pragma unroll
            for (int j = 0; j < 4; j++) {
                float p = __expf(sacc[i][j] - mx);
                sacc[i][j] = p;
                ls += p;
            }
#pragma unroll
            for (int s = 1; s < 16; s <<= 1)
                ls += __shfl_xor_sync(0xFFFFFFFFu, ls, s);
            rl[i] = rl[i] * fac[i] + ls;
        }

#pragma unroll
        for (int i = 0; i < 4; i++)
#pragma unroll
            for (int j = 0; j < 4; j++)
                Ps[(ty * 4 + i) * 65 + tx * 4 + j] = sacc[i][j];

#pragma unroll
        for (int i = 0; i < 4; i++)
#pragma unroll
            for (int j = 0; j < 4; j++) oacc[i][j] *= fac[i];

        __syncthreads();

#pragma unroll 8
        for (int j = 0; j < 64; j++) {
            float p[4];
#pragma unroll
            for (int i = 0; i < 4; i++) p[i] = Ps[(ty * 4 + i) * 65 + j];
            float4 v = *(const float4*)&Vs[j * 64 + tx * 4];
            float vv[4] = {v.x, v.y, v.z, v.w};
#pragma unroll
            for (int i = 0; i < 4; i++)
#pragma unroll
                for (int jj = 0; jj < 4; jj++)
                    oacc[i][jj] = fmaf(p[i], vv[jj], oacc[i][jj]);
        }
    }

#pragma unroll
    for (int i = 0; i < 4; i++) {
        const float linv = 1.0f / rl[i];
        const size_t row = (size_t)b * SEQ + q0 + ty * 4 + i;
        float4 o;
        o.x = oacc[i][0] * linv;
        o.y = oacc[i][1] * linv;
        o.z = oacc[i][2] * linv;
        o.w = oacc[i][3] * linv;
        *(float4*)(out + row * EMBED + h * HDIM + tx * 4) = o;
    }
}

// ---------------------------------------------------------------------------
// Launch
// ---------------------------------------------------------------------------
extern "C" void kernel_launch(void* const* d_in, const int* in_sizes, int n_in,
                              void* d_out, int out_size)
{
    const float* x      = (const float*)d_in[0];  // [4,2048,1024]
    const float* w_qkv  = (const float*)d_in[1];  // [1024,3072]
    const float* b_qkv  = (const float*)d_in[2];  // [3072]
    const float* w_proj = (const float*)d_in[3];  // [1024,1024]
    const float* b_proj = (const float*)d_in[4];  // [1024]
    float* out = (float*)d_out;                   // [8192,1024]

    float *g1 = nullptr, *g2 = nullptr;
    cudaGetSymbolAddress((void**)&g1, g_qkv);
    cudaGetSymbolAddress((void**)&g2, g_att);

    const int M = BATCH * SEQ;   // 8192

    cudaFuncSetAttribute(gemm_mma_kernel, cudaFuncAttributeMaxDynamicSharedMemorySize,
                         GM_SMEM);

    // 1) QKV projection: [8192,1024] @ [1024,3072] + b  (tf32 mma.sync)
    gemm_mma_kernel<<<dim3(3 * EMBED / 128, M / 128), 256, GM_SMEM>>>(
        x, w_qkv, b_qkv, g1, M, 3 * EMBED, EMBED);

    // 2) Flash attention (fp32 SIMT)
    size_t smem = (size_t)(64 * 68 * 2 + 64 * 65 + 64 * 64) * sizeof(float);
    cudaFuncSetAttribute(attn_kernel, cudaFuncAttributeMaxDynamicSharedMemorySize, (int)smem);
    attn_kernel<<<dim3(SEQ / 64, NHEADS, BATCH), 256, smem>>>(g1, g2);

    // 3) Output projection: [8192,1024] @ [1024,1024] + b  (tf32 mma.sync)
    gemm_mma_kernel<<<dim3(EMBED / 128, M / 128), 256, GM_SMEM>>>(
        g2, w_proj, b_proj, out, M, EMBED, EMBED);
}

// round 15
// speedup vs baseline: 2.2713x; 1.8399x over previous
#include <cuda_runtime.h>
#include <cuda_bf16.h>
#include <cstdint>

// Problem constants
#define EMBED   1024
#define NHEADS  16
#define HDIM    64
#define BATCH   4
#define SEQ     2048
#define QKSCALE 0.125f   // 1/sqrt(64)

// Scratch (device globals: allocation-free per harness rules)
__device__ float g_qkv[(size_t)BATCH * SEQ * 3 * EMBED];  // [B*N, 3C]
__device__ float g_att[(size_t)BATCH * SEQ * EMBED];      // [B*N, C]

// round fp32 -> tf32 (RNA) — plain sm_80+ instruction, no 'a' gating
__device__ __forceinline__ float f2tf32f(float x) {
    uint32_t r;
    asm("cvt.rna.tf32.f32 %0, %1;" : "=r"(r) : "f"(x));
    return __uint_as_float(r);
}

// m16n8k8 tf32 MMA (sm_80+ baseline PTX; runs on tensor pipe on sm_103)
__device__ __forceinline__ void mma_tf32(float* d, const uint32_t* a, const uint32_t* b) {
    asm volatile(
        "mma.sync.aligned.m16n8k8.row.col.f32.tf32.tf32.f32 "
        "{%0,%1,%2,%3}, {%4,%5,%6,%7}, {%8,%9}, {%0,%1,%2,%3};"
        : "+f"(d[0]), "+f"(d[1]), "+f"(d[2]), "+f"(d[3])
        : "r"(a[0]), "r"(a[1]), "r"(a[2]), "r"(a[3]), "r"(b[0]), "r"(b[1]));
}

// ===========================================================================
// tf32 mma.sync GEMM: C[M,N] = A[M,K] @ W[K,N] + bias[N]   (R7: verified good)
// ===========================================================================
#define AS_PITCH 36
#define BS_PITCH 136
#define AS_STRIDE (128 * AS_PITCH)
#define BS_STRIDE (32 * BS_PITCH)
#define GM_SMEM ((2 * AS_STRIDE + 2 * BS_STRIDE) * 4)

__global__ __launch_bounds__(256)
void gemm_mma_kernel(const float* __restrict__ A, const float* __restrict__ W,
                     const float* __restrict__ bias, float* __restrict__ C,
                     int M, int N, int K)
{
    extern __shared__ float sh[];
    float* As = sh;
    float* Bs = sh + 2 * AS_STRIDE;

    const int t    = threadIdx.x;
    const int wid  = t >> 5;
    const int lane = t & 31;
    const int wm   = (wid >> 2) * 64;
    const int wn   = (wid & 3) * 32;
    const int m0   = blockIdx.y * 128;
    const int n0   = blockIdx.x * 128;
    const int g    = lane >> 2;
    const int tq   = lane & 3;

    const int arow = t >> 1;
    const int acol = (t & 1) * 16;
    const int brow = t >> 3;
    const int bcol = (t & 7) * 16;

    const float* Ap = A + (size_t)(m0 + arow) * K + acol;
    const float* Wp = W + (size_t)brow * N + n0 + bcol;

    float acc[16][4];
#pragma unroll
    for (int i = 0; i < 16; i++)
#pragma unroll
        for (int j = 0; j < 4; j++) acc[i][j] = 0.0f;

    float4 ra[4], rb[4];

#pragma unroll
    for (int i = 0; i < 4; i++) {
        ra[i] = *(const float4*)(Ap + i * 4);
        rb[i] = *(const float4*)(Wp + i * 4);
    }
    {
        float* ad = As + arow * AS_PITCH + acol;
        float* bd = Bs + brow * BS_PITCH + bcol;
#pragma unroll
        for (int i = 0; i < 4; i++) {
            float4 va, vb;
            va.x = f2tf32f(ra[i].x); va.y = f2tf32f(ra[i].y);
            va.z = f2tf32f(ra[i].z); va.w = f2tf32f(ra[i].w);
            vb.x = f2tf32f(rb[i].x); vb.y = f2tf32f(rb[i].y);
            vb.z = f2tf32f(rb[i].z); vb.w = f2tf32f(rb[i].w);
            *(float4*)(ad + i * 4) = va;
            *(float4*)(bd + i * 4) = vb;
        }
    }
    __syncthreads();

    const int nch = K >> 5;
    for (int ci = 0; ci < nch; ci++) {
        const int s = ci & 1;

        if (ci + 1 < nch) {
            const int k0 = (ci + 1) << 5;
#pragma unroll
            for (int i = 0; i < 4; i++) {
                ra[i] = *(const float4*)(Ap + k0 + i * 4);
                rb[i] = *(const float4*)(Wp + (size_t)k0 * N + i * 4);
            }
        }

        const float* as = As + s * AS_STRIDE;
        const float* bs = Bs + s * BS_STRIDE;
#pragma unroll
        for (int k8 = 0; k8 < 4; k8++) {
            uint32_t af[4][4], bf[4][2];
#pragma unroll
            for (int mi = 0; mi < 4; mi++) {
                const float* ap = as + (wm + mi * 16 + g) * AS_PITCH + k8 * 8 + tq;
                af[mi][0] = __float_as_uint(ap[0]);
                af[mi][1] = __float_as_uint(ap[8 * AS_PITCH]);
                af[mi][2] = __float_as_uint(ap[4]);
                af[mi][3] = __float_as_uint(ap[8 * AS_PITCH + 4]);
            }
#pragma unroll
            for (int ni = 0; ni < 4; ni++) {
                const float* bp = bs + (k8 * 8 + tq) * BS_PITCH + wn + ni * 8 + g;
                bf[ni][0] = __float_as_uint(bp[0]);
                bf[ni][1] = __float_as_uint(bp[4 * BS_PITCH]);
            }
#pragma unroll
            for (int mi = 0; mi < 4; mi++)
#pragma unroll
                for (int ni = 0; ni < 4; ni++)
                    mma_tf32(acc[mi * 4 + ni], af[mi], bf[ni]);
        }

        if (ci + 1 < nch) {
            float* ad = As + (s ^ 1) * AS_STRIDE + arow * AS_PITCH + acol;
            float* bd = Bs + (s ^ 1) * BS_STRIDE + brow * BS_PITCH + bcol;
#pragma unroll
            for (int i = 0; i < 4; i++) {
                float4 va, vb;
                va.x = f2tf32f(ra[i].x); va.y = f2tf32f(ra[i].y);
                va.z = f2tf32f(ra[i].z); va.w = f2tf32f(ra[i].w);
                vb.x = f2tf32f(rb[i].x); vb.y = f2tf32f(rb[i].y);
                vb.z = f2tf32f(rb[i].z); vb.w = f2tf32f(rb[i].w);
                *(float4*)(ad + i * 4) = va;
                *(float4*)(bd + i * 4) = vb;
            }
        }
        __syncthreads();
    }

#pragma unroll
    for (int mi = 0; mi < 4; mi++) {
#pragma unroll
        for (int ni = 0; ni < 4; ni++) {
            const int col  = n0 + wn + ni * 8 + tq * 2;
            const float2 bv = *(const float2*)(bias + col);
            const int row1 = m0 + wm + mi * 16 + g;
            const float* a4 = acc[mi * 4 + ni];
            float2 o1, o2;
            o1.x = a4[0] + bv.x; o1.y = a4[1] + bv.y;
            o2.x = a4[2] + bv.x; o2.y = a4[3] + bv.y;
            *(float2*)(C + (size_t)row1 * N + col)       = o1;
            *(float2*)(C + (size_t)(row1 + 8) * N + col) = o2;
        }
    }
}

// ===========================================================================
// Flash attention, tf32 mma.sync.
// Block = 128 q-rows x (head, batch). 8 warps, each owns a 16-row band.
// 64-key tiles, 32 iterations, K/V double-buffered with register staging.
// SMEM: Qs[row][d] p68 (A-frag banks 4g+tq), Ks[d][key] p72 (B-frag 8tq+g),
//       Vs[key][d] p72, Ps[row][key] p68. All fragment LDS conflict-free.
// ===========================================================================
#define BQ 128
#define BKEY 64
#define QS_PITCH 68
#define KV_PITCH 72
#define ATTN_SMEM ((2 * BQ * QS_PITCH + 4 * BKEY * KV_PITCH) * 4)  // 143360 B

__global__ __launch_bounds__(256)
void attn_mma_kernel(const float* __restrict__ qkv, float* __restrict__ out)
{
    extern __shared__ float sh[];
    float* Qs = sh;                                   // [128][68]
    float* Ks = Qs + BQ * QS_PITCH;                   // [2][64][72]  Ks[d][key]
    float* Vs = Ks + 2 * BKEY * KV_PITCH;             // [2][64][72]  Vs[key][d]
    float* Ps = Vs + 2 * BKEY * KV_PITCH;             // [128][68]

    const int t    = threadIdx.x;
    const int wid  = t >> 5;
    const int lane = t & 31;
    const int g    = lane >> 2;
    const int tq   = lane & 3;
    const int wrow = wid * 16;
    const int q0   = blockIdx.x * BQ;
    const int h    = blockIdx.y;
    const int b    = blockIdx.z;

    const size_t rstride = 3 * EMBED;
    const float* base  = qkv + (size_t)b * SEQ * rstride + h * HDIM;
    const float* kbase = base + EMBED;
    const float* vbase = base + 2 * EMBED;

    // Load Q (tf32 + scale): thread -> row t>>1, 32-col half
    {
        const int r  = t >> 1;
        const int c0 = (t & 1) * 32;
        const float* qp = base + (size_t)(q0 + r) * rstride + c0;
        float* qd = Qs + r * QS_PITCH + c0;
#pragma unroll
        for (int x = 0; x < 32; x += 4) {
            float4 v = *(const float4*)(qp + x);
            qd[x + 0] = f2tf32f(v.x * QKSCALE);
            qd[x + 1] = f2tf32f(v.y * QKSCALE);
            qd[x + 2] = f2tf32f(v.z * QKSCALE);
            qd[x + 3] = f2tf32f(v.w * QKSCALE);
        }
    }

    // K/V load mapping: key row kj = t>>2, 16-col group kc
    const int kj = t >> 2;
    const int kc = (t & 3) * 16;

    float4 kr[4], vr[4];
    // Prologue: tile 0 -> regs -> stage 0
    {
        const float* kp = kbase + (size_t)kj * rstride + kc;
        const float* vp = vbase + (size_t)kj * rstride + kc;
#pragma unroll
        for (int i = 0; i < 4; i++) {
            kr[i] = *(const float4*)(kp + i * 4);
            vr[i] = *(const float4*)(vp + i * 4);
        }
    }
    {
        float* kd = Ks;   // stage 0
        float* vd = Vs;
#pragma unroll
        for (int i = 0; i < 4; i++) {
            kd[(kc + i * 4 + 0) * KV_PITCH + kj] = f2tf32f(kr[i].x);
            kd[(kc + i * 4 + 1) * KV_PITCH + kj] = f2tf32f(kr[i].y);
            kd[(kc + i * 4 + 2) * KV_PITCH + kj] = f2tf32f(kr[i].z);
            kd[(kc + i * 4 + 3) * KV_PITCH + kj] = f2tf32f(kr[i].w);
            float4 vc;
            vc.x = f2tf32f(vr[i].x); vc.y = f2tf32f(vr[i].y);
            vc.z = f2tf32f(vr[i].z); vc.w = f2tf32f(vr[i].w);
            *(float4*)(vd + kj * KV_PITCH + kc + i * 4) = vc;
        }
    }
    __syncthreads();

    float o[8][4];
#pragma unroll
    for (int i = 0; i < 8; i++)
#pragma unroll
        for (int j = 0; j < 4; j++) o[i][j] = 0.0f;
    float rm0 = -1e30f, rm1 = -1e30f, rl0 = 0.0f, rl1 = 0.0f;

    const int NT = SEQ / BKEY;   // 32
    for (int kt = 0; kt < NT; kt++) {
        const int s = kt & 1;

        // Prefetch next K/V tile into registers (overlaps compute)
        if (kt + 1 < NT) {
            const float* kp = kbase + (size_t)((kt + 1) * BKEY + kj) * rstride + kc;
            const float* vp = vbase + (size_t)((kt + 1) * BKEY + kj) * rstride + kc;
#pragma unroll
            for (int i = 0; i < 4; i++) {
                kr[i] = *(const float4*)(kp + i * 4);
                vr[i] = *(const float4*)(vp + i * 4);
            }
        }

        const float* ks = Ks + s * BKEY * KV_PITCH;
        const float* vs = Vs + s * BKEY * KV_PITCH;

        // ---- S = Q @ K^T (16 rows x 64 cols per warp) ----
        float sa[8][4];
#pragma unroll
        for (int i = 0; i < 8; i++)
#pragma unroll
            for (int j = 0; j < 4; j++) sa[i][j] = 0.0f;

#pragma unroll
        for (int kk = 0; kk < 8; kk++) {
            uint32_t af[4];
            const float* qp = Qs + (wrow + g) * QS_PITCH + kk * 8 + tq;
            af[0] = __float_as_uint(qp[0]);
            af[1] = __float_as_uint(qp[8 * QS_PITCH]);
            af[2] = __float_as_uint(qp[4]);
            af[3] = __float_as_uint(qp[8 * QS_PITCH + 4]);
#pragma unroll
            for (int ni = 0; ni < 8; ni++) {
                uint32_t bf[2];
                const float* bp = ks + (kk * 8 + tq) * KV_PITCH + ni * 8 + g;
                bf[0] = __float_as_uint(bp[0]);
                bf[1] = __float_as_uint(bp[4 * KV_PITCH]);
                mma_tf32(sa[ni], af, bf);
            }
        }

        // ---- online softmax (rows wrow+g and wrow+g+8; quad shfl) ----
        float mx0 = -1e30f, mx1 = -1e30f;
#pragma unroll
        for (int ni = 0; ni < 8; ni++) {
            mx0 = fmaxf(mx0, fmaxf(sa[ni][0], sa[ni][1]));
            mx1 = fmaxf(mx1, fmaxf(sa[ni][2], sa[ni][3]));
        }
        mx0 = fmaxf(mx0, __shfl_xor_sync(0xFFFFFFFFu, mx0, 1));
        mx0 = fmaxf(mx0, __shfl_xor_sync(0xFFFFFFFFu, mx0, 2));
        mx1 = fmaxf(mx1, __shfl_xor_sync(0xFFFFFFFFu, mx1, 1));
        mx1 = fmaxf(mx1, __shfl_xor_sync(0xFFFFFFFFu, mx1, 2));

        const float mn0 = fmaxf(rm0, mx0);
        const float mn1 = fmaxf(rm1, mx1);
        const float f0 = __expf(rm0 - mn0);
        const float f1 = __expf(rm1 - mn1);
        rm0 = mn0; rm1 = mn1;

        float s0 = 0.0f, s1 = 0.0f;
#pragma unroll
        for (int ni = 0; ni < 8; ni++) {
            float p0 = __expf(sa[ni][0] - mn0);
            float p1 = __expf(sa[ni][1] - mn0);
            float p2 = __expf(sa[ni][2] - mn1);
            float p3 = __expf(sa[ni][3] - mn1);
            sa[ni][0] = p0; sa[ni][1] = p1; sa[ni][2] = p2; sa[ni][3] = p3;
            s0 += p0 + p1;
            s1 += p2 + p3;
        }
        s0 += __shfl_xor_sync(0xFFFFFFFFu, s0, 1);
        s0 += __shfl_xor_sync(0xFFFFFFFFu, s0, 2);
        s1 += __shfl_xor_sync(0xFFFFFFFFu, s1, 1);
        s1 += __shfl_xor_sync(0xFFFFFFFFu, s1, 2);
        rl0 = rl0 * f0 + s0;
        rl1 = rl1 * f1 + s1;

        // rescale O
#pragma unroll
        for (int ni = 0; ni < 8; ni++) {
            o[ni][0] *= f0; o[ni][1] *= f0;
            o[ni][2] *= f1; o[ni][3] *= f1;
        }

        // P -> smem (warp-private rows), tf32
#pragma unroll
        for (int ni = 0; ni < 8; ni++) {
            float2 p01, p23;
            p01.x = f2tf32f(sa[ni][0]); p01.y = f2tf32f(sa[ni][1]);
            p23.x = f2tf32f(sa[ni][2]); p23.y = f2tf32f(sa[ni][3]);
            *(float2*)&Ps[(wrow + g) * QS_PITCH + ni * 8 + tq * 2]     = p01;
            *(float2*)&Ps[(wrow + g + 8) * QS_PITCH + ni * 8 + tq * 2] = p23;
        }
        __syncwarp();

        // ---- O += P @ V ----
#pragma unroll
        for (int kk = 0; kk < 8; kk++) {
            uint32_t af[4];
            const float* pp = Ps + (wrow + g) * QS_PITCH + kk * 8 + tq;
            af[0] = __float_as_uint(pp[0]);
            af[1] = __float_as_uint(pp[8 * QS_PITCH]);
            af[2] = __float_as_uint(pp[4]);
            af[3] = __float_as_uint(pp[8 * QS_PITCH + 4]);
#pragma unroll
            for (int ni = 0; ni < 8; ni++) {
                uint32_t bf[2];
                const float* bp = vs + (kk * 8 + tq) * KV_PITCH + ni * 8 + g;
                bf[0] = __float_as_uint(bp[0]);
                bf[1] = __float_as_uint(bp[4 * KV_PITCH]);
                mma_tf32(o[ni], af, bf);
            }
        }

        // ---- stage next tile ----
        if (kt + 1 < NT) {
            float* kd = Ks + (s ^ 1) * BKEY * KV_PITCH;
            float* vd = Vs + (s ^ 1) * BKEY * KV_PITCH;
#pragma unroll
            for (int i = 0; i < 4; i++) {
                kd[(kc + i * 4 + 0) * KV_PITCH + kj] = f2tf32f(kr[i].x);
                kd[(kc + i * 4 + 1) * KV_PITCH + kj] = f2tf32f(kr[i].y);
                kd[(kc + i * 4 + 2) * KV_PITCH + kj] = f2tf32f(kr[i].z);
                kd[(kc + i * 4 + 3) * KV_PITCH + kj] = f2tf32f(kr[i].w);
                float4 vc;
                vc.x = f2tf32f(vr[i].x); vc.y = f2tf32f(vr[i].y);
                vc.z = f2tf32f(vr[i].z); vc.w = f2tf32f(vr[i].w);
                *(float4*)(vd + kj * KV_PITCH + kc + i * 4) = vc;
            }
        }
        __syncthreads();
    }

    // ---- epilogue: normalize + store ----
    const float li0 = 1.0f / rl0;
    const float li1 = 1.0f / rl1;
    float* orow0 = out + (size_t)(b * SEQ + q0 + wrow + g) * EMBED + h * HDIM;
    float* orow1 = orow0 + (size_t)8 * EMBED;
#pragma unroll
    for (int ni = 0; ni < 8; ni++) {
        float2 w0, w1;
        w0.x = o[ni][0] * li0; w0.y = o[ni][1] * li0;
        w1.x = o[ni][2] * li1; w1.y = o[ni][3] * li1;
        *(float2*)(orow0 + ni * 8 + tq * 2) = w0;
        *(float2*)(orow1 + ni * 8 + tq * 2) = w1;
    }
}

// ---------------------------------------------------------------------------
// Launch
// ---------------------------------------------------------------------------
extern "C" void kernel_launch(void* const* d_in, const int* in_sizes, int n_in,
                              void* d_out, int out_size)
{
    const float* x      = (const float*)d_in[0];  // [4,2048,1024]
    const float* w_qkv  = (const float*)d_in[1];  // [1024,3072]
    const float* b_qkv  = (const float*)d_in[2];  // [3072]
    const float* w_proj = (const float*)d_in[3];  // [1024,1024]
    const float* b_proj = (const float*)d_in[4];  // [1024]
    float* out = (float*)d_out;                   // [8192,1024]

    float *g1 = nullptr, *g2 = nullptr;
    cudaGetSymbolAddress((void**)&g1, g_qkv);
    cudaGetSymbolAddress((void**)&g2, g_att);

    const int M = BATCH * SEQ;   // 8192

    cudaFuncSetAttribute(gemm_mma_kernel, cudaFuncAttributeMaxDynamicSharedMemorySize,
                         GM_SMEM);
    cudaFuncSetAttribute(attn_mma_kernel, cudaFuncAttributeMaxDynamicSharedMemorySize,
                         ATTN_SMEM);

    // 1) QKV projection (tf32 mma.sync)
    gemm_mma_kernel<<<dim3(3 * EMBED / 128, M / 128), 256, GM_SMEM>>>(
        x, w_qkv, b_qkv, g1, M, 3 * EMBED, EMBED);

    // 2) Flash attention (tf32 mma.sync)
    attn_mma_kernel<<<dim3(SEQ / BQ, NHEADS, BATCH), 256, ATTN_SMEM>>>(g1, g2);

    // 3) Output projection (tf32 mma.sync)
    gemm_mma_kernel<<<dim3(EMBED / 128, M / 128), 256, GM_SMEM>>>(
        g2, w_proj, b_proj, out, M, EMBED, EMBED);
}